// round 6
// baseline (speedup 1.0000x reference)
// R6 resubmission: identical to R5 occupancy kernel — R5 bench was an infra
// failure (GB300 container failed twice), no measurement obtained.
// 512-thread blocks, 4x8 thread tiles, 64-reg cap, 32 warps/SM.
// Arithmetic identical to R2/R4 (rel_err 0.0).
#include <cuda_runtime.h>
#include <cstdint>

#define BM 128
#define BK 128
#define DCH 16
#define D_DIM 256
#define K_CODES 1024
#define HW 1024
#define NCHUNK (D_DIM / DCH)     // 16
#define NKT (K_CODES / BK)       // 8
#define NST (NKT * NCHUNK)       // 128 pipeline stages
#define THREADS 512

// Scratch (allocations forbidden; __device__ globals are the sanctioned path)
__device__ float g_eT[D_DIM * K_CODES];   // codebook transposed [d][k]
__device__ float g_e2[K_CODES];           // ||e_k||^2

__global__ void vq_prep(const float* __restrict__ emb) {
    const int j = blockIdx.x;
    const int d = threadIdx.x;
    float v = emb[j * D_DIM + d];
    g_eT[d * K_CODES + j] = v;
    float s = __fmul_rn(v, v);
    #pragma unroll
    for (int o = 16; o > 0; o >>= 1)
        s = __fadd_rn(s, __shfl_down_sync(0xFFFFFFFFu, s, o));
    __shared__ float ws[8];
    if ((d & 31) == 0) ws[d >> 5] = s;
    __syncthreads();
    if (d == 0) {
        float t = ws[0];
        #pragma unroll
        for (int w = 1; w < 8; w++) t = __fadd_rn(t, ws[w]);
        g_e2[j] = t;
    }
}

__device__ __forceinline__ void cp_async16_ca(uint32_t dst, const void* src) {
    asm volatile("cp.async.ca.shared.global [%0], [%1], 16;\n" :: "r"(dst), "l"(src));
}
__device__ __forceinline__ void cp_async16_cg(uint32_t dst, const void* src) {
    asm volatile("cp.async.cg.shared.global [%0], [%1], 16;\n" :: "r"(dst), "l"(src));
}
__device__ __forceinline__ void cp_commit() {
    asm volatile("cp.async.commit_group;\n" ::: "memory");
}
__device__ __forceinline__ void cp_wait0() {
    asm volatile("cp.async.wait_group 0;\n" ::: "memory");
}

// Packed f32x2: each lane is a standard rn fp32 FMA — bit-identical to
// __fmaf_rn, exactness preserved.
__device__ __forceinline__ unsigned long long pack2(float lo, float hi) {
    unsigned long long r;
    asm("mov.b64 %0, {%1, %2};" : "=l"(r) : "f"(lo), "f"(hi));
    return r;
}
__device__ __forceinline__ void unpack2(unsigned long long v, float& lo, float& hi) {
    asm("mov.b64 {%0, %1}, %2;" : "=f"(lo), "=f"(hi) : "l"(v));
}
__device__ __forceinline__ unsigned long long fma2(unsigned long long a,
                                                   unsigned long long b,
                                                   unsigned long long c) {
    unsigned long long d;
    asm("fma.rn.f32x2 %0, %1, %2, %3;" : "=l"(d) : "l"(a), "l"(b), "l"(c));
    return d;
}

// 512 threads: tx = code-group (16 x 8 codes), ty = row-group (32 x 4 rows).
__global__ void __launch_bounds__(THREADS, 2) vq_main(
    const float* __restrict__ z, const float* __restrict__ emb,
    float* __restrict__ zq, float* __restrict__ idxf, float* __restrict__ loss)
{
    __shared__ float zs[2][DCH][BM];           // 16 KB
    __shared__ float es[2][DCH][BK];           // 16 KB
    __shared__ float szs[BM];
    __shared__ unsigned long long rmin[BM];

    const int tid = threadIdx.x;
    const int tx = tid & 15;                   // 0..15 (8 codes each)
    const int ty = tid >> 4;                   // 0..31 (4 rows each)
    const int nbase = blockIdx.x * BM;
    const int b = nbase / HW;
    const int hwbase = nbase % HW;
    const float* zb = z + (size_t)b * (D_DIM * HW) + hwbase;

    // loader: one float4 per thread per array per stage (512 x 16B = 8 KB)
    const int lr = tid >> 5;                   // 0..15 (d within chunk)
    const int lc = (tid & 31) << 2;            // 0..124

    const uint32_t zs_smem = (uint32_t)__cvta_generic_to_shared(&zs[0][0][0]);
    const uint32_t es_smem = (uint32_t)__cvta_generic_to_shared(&es[0][0][0]);

    // Stage 0 load overlaps the ||z||^2 pass.
    cp_async16_ca(zs_smem + (lr * BM + lc) * 4, &zb[(size_t)lr * HW + lc]);
    cp_async16_cg(es_smem + (lr * BK + lc) * 4, &g_eT[lr * K_CODES + lc]);
    cp_commit();

    // Per-row ||z||^2: sequential over d, rounded squares (exactness-critical).
    if (tid < BM) {
        rmin[tid] = ~0ULL;
        float s = 0.f;
        const float* zp = zb + tid;
        for (int d = 0; d < D_DIM; d++) {
            float v = zp[(size_t)d * HW];
            s = __fadd_rn(s, __fmul_rn(v, v));
        }
        szs[tid] = s;
    }
    __syncthreads();

    float minv[4];
    unsigned minj[4];
    #pragma unroll
    for (int i = 0; i < 4; i++) { minv[i] = 3.402823466e38f; minj[i] = 0u; }

    unsigned long long acc2[4][4];             // [row][code-pair]

    for (int s = 0; s < NST; s++) {
        const int buf = s & 1;
        const int chunk = s & (NCHUNK - 1);
        const int kt = (s >> 4) * BK;

        cp_wait0();
        __syncthreads();

        if (s + 1 < NST) {
            const int nb = (s + 1) & 1;
            const int nd0 = ((s + 1) & (NCHUNK - 1)) * DCH;
            const int nkt = ((s + 1) >> 4) * BK;
            cp_async16_ca(zs_smem + ((nb * DCH + lr) * BM + lc) * 4,
                          &zb[(size_t)(nd0 + lr) * HW + lc]);
            cp_async16_cg(es_smem + ((nb * DCH + lr) * BK + lc) * 4,
                          &g_eT[(nd0 + lr) * K_CODES + nkt + lc]);
            cp_commit();
        }

        if (chunk == 0) {
            #pragma unroll
            for (int i = 0; i < 4; i++)
                #pragma unroll
                for (int j = 0; j < 4; j++) acc2[i][j] = 0ULL;
        }

        #pragma unroll
        for (int dd = 0; dd < DCH; dd++) {
            float4 za = *(float4*)&zs[buf][dd][ty * 4];
            const unsigned long long* ep =
                (const unsigned long long*)&es[buf][dd][tx * 8];
            unsigned long long er0 = ep[0], er1 = ep[1], er2v = ep[2], er3 = ep[3];
            float zr[4] = {za.x, za.y, za.z, za.w};
            #pragma unroll
            for (int i = 0; i < 4; i++) {
                unsigned long long zz = pack2(zr[i], zr[i]);
                acc2[i][0] = fma2(zz, er0,  acc2[i][0]);
                acc2[i][1] = fma2(zz, er1,  acc2[i][1]);
                acc2[i][2] = fma2(zz, er2v, acc2[i][2]);
                acc2[i][3] = fma2(zz, er3,  acc2[i][3]);
            }
        }

        if (chunk == NCHUNK - 1) {
            // Identical scalar distance + strict-< ascending-code argmin.
            #pragma unroll
            for (int j2 = 0; j2 < 4; j2++) {
                const int code0 = kt + tx * 8 + j2 * 2;
                const float e2a = g_e2[code0];
                const float e2b = g_e2[code0 + 1];
                #pragma unroll
                for (int i = 0; i < 4; i++) {
                    const float szr = szs[ty * 4 + i];
                    float dlo, dhi;
                    unpack2(acc2[i][j2], dlo, dhi);
                    float t0 = __fadd_rn(szr, e2a);
                    float dist0 = __fmaf_rn(-2.0f, dlo, t0);
                    if (dist0 < minv[i]) { minv[i] = dist0; minj[i] = (unsigned)code0; }
                    float t1 = __fadd_rn(szr, e2b);
                    float dist1 = __fmaf_rn(-2.0f, dhi, t1);
                    if (dist1 < minv[i]) { minv[i] = dist1; minj[i] = (unsigned)(code0 + 1); }
                }
            }
        }
    }

    // Cross-thread reduce: packed ordered-float | idx, atomicMin
    // (min picks lowest index on exact ties — reference tie-break).
    #pragma unroll
    for (int i = 0; i < 4; i++) {
        unsigned fb = __float_as_uint(minv[i]);
        fb = (fb & 0x80000000u) ? ~fb : (fb | 0x80000000u);
        unsigned long long p =
            ((unsigned long long)fb << 32) | (unsigned long long)minj[i];
        atomicMin(&rmin[ty * 4 + i], p);
    }
    __syncthreads();

    // Epilogue: 4 threads per row, 64 d's each.
    const int r = tid & 127;
    const int q = tid >> 7;                    // 0..3
    const int n = nbase + r;
    const unsigned code = (unsigned)(rmin[r] & 0xFFFFFFFFu);
    if (q == 0) idxf[n] = (float)code;
    const float* erow = emb + (size_t)code * D_DIM;
    float* zqb = zq + (size_t)b * (D_DIM * HW) + hwbase;
    float* lrow = loss + (size_t)n * D_DIM;
    #pragma unroll 4
    for (int sft = 0; sft < D_DIM / 4; sft++) {
        const int d = q * (D_DIM / 4) + sft;
        float zv = zb[(size_t)d * HW + r];
        float ev = __ldg(&erow[d]);
        zqb[(size_t)d * HW + r] = ev;
        float df = __fadd_rn(ev, -zv);
        lrow[d] = __fmul_rn(df, df);
    }
}

extern "C" void kernel_launch(void* const* d_in, const int* in_sizes, int n_in,
                              void* d_out, int out_size) {
    const float* z   = (const float*)d_in[0];   // [32,256,32,32]
    const float* emb = (const float*)d_in[1];   // [1024,256]
    float* out = (float*)d_out;

    const int n_z = in_sizes[0];                // 8388608
    const int N = n_z / D_DIM;                  // 32768

    float* zq   = out;
    float* idxf = out + n_z;
    float* loss = out + n_z + N;

    vq_prep<<<K_CODES, D_DIM>>>(emb);
    vq_main<<<N / BM, THREADS>>>(z, emb, zq, idxf, loss);
}

// round 7
// speedup vs baseline: 1.7211x; 1.7211x over previous
// R7: revert to R4 structure (256 thr, 8x8, FFMA2) + bank-conflict-free
// code-pair interleaving: thread tx owns pairs {tx+16*j2}, so each es
// fragment load is a contiguous 128B warp read (1 phase vs 4).
#include <cuda_runtime.h>
#include <cstdint>

#define BM 128
#define BK 128
#define DCH 16
#define D_DIM 256
#define K_CODES 1024
#define HW 1024
#define NCHUNK (D_DIM / DCH)     // 16
#define NKT (K_CODES / BK)       // 8
#define NST (NKT * NCHUNK)       // 128 pipeline stages

__device__ float g_eT[D_DIM * K_CODES];   // codebook transposed [d][k]
__device__ float g_e2[K_CODES];           // ||e_k||^2

__global__ void vq_prep(const float* __restrict__ emb) {
    const int j = blockIdx.x;
    const int d = threadIdx.x;
    float v = emb[j * D_DIM + d];
    g_eT[d * K_CODES + j] = v;
    float s = __fmul_rn(v, v);
    #pragma unroll
    for (int o = 16; o > 0; o >>= 1)
        s = __fadd_rn(s, __shfl_down_sync(0xFFFFFFFFu, s, o));
    __shared__ float ws[8];
    if ((d & 31) == 0) ws[d >> 5] = s;
    __syncthreads();
    if (d == 0) {
        float t = ws[0];
        #pragma unroll
        for (int w = 1; w < 8; w++) t = __fadd_rn(t, ws[w]);
        g_e2[j] = t;
    }
}

__device__ __forceinline__ void cp_async16_ca(uint32_t dst, const void* src) {
    asm volatile("cp.async.ca.shared.global [%0], [%1], 16;\n" :: "r"(dst), "l"(src));
}
__device__ __forceinline__ void cp_async16_cg(uint32_t dst, const void* src) {
    asm volatile("cp.async.cg.shared.global [%0], [%1], 16;\n" :: "r"(dst), "l"(src));
}
__device__ __forceinline__ void cp_commit() {
    asm volatile("cp.async.commit_group;\n" ::: "memory");
}
__device__ __forceinline__ void cp_wait0() {
    asm volatile("cp.async.wait_group 0;\n" ::: "memory");
}

// Packed f32x2: each lane is a standard rn fp32 FMA — bit-identical to
// __fmaf_rn, exactness preserved.
__device__ __forceinline__ unsigned long long pack2(float lo, float hi) {
    unsigned long long r;
    asm("mov.b64 %0, {%1, %2};" : "=l"(r) : "f"(lo), "f"(hi));
    return r;
}
__device__ __forceinline__ void unpack2(unsigned long long v, float& lo, float& hi) {
    asm("mov.b64 {%0, %1}, %2;" : "=f"(lo), "=f"(hi) : "l"(v));
}
__device__ __forceinline__ unsigned long long fma2(unsigned long long a,
                                                   unsigned long long b,
                                                   unsigned long long c) {
    unsigned long long d;
    asm("fma.rn.f32x2 %0, %1, %2, %3;" : "=l"(d) : "l"(a), "l"(b), "l"(c));
    return d;
}

__global__ void __launch_bounds__(256, 2) vq_main(
    const float* __restrict__ z, const float* __restrict__ emb,
    float* __restrict__ zq, float* __restrict__ idxf, float* __restrict__ loss)
{
    __shared__ float zs[2][DCH][BM];           // 16 KB
    __shared__ float es[2][DCH][BK];           // 16 KB
    __shared__ float szs[BM];
    __shared__ unsigned long long rmin[BM];

    const int tid = threadIdx.x;
    const int tx = tid & 15;
    const int ty = tid >> 4;
    const int nbase = blockIdx.x * BM;
    const int b = nbase / HW;
    const int hwbase = nbase % HW;
    const float* zb = z + (size_t)b * (D_DIM * HW) + hwbase;

    const int lr = tid >> 5;                   // 0..7
    const int lc = (tid & 31) << 2;            // 0..124

    const uint32_t zs_smem = (uint32_t)__cvta_generic_to_shared(&zs[0][0][0]);
    const uint32_t es_smem = (uint32_t)__cvta_generic_to_shared(&es[0][0][0]);

    // Stage 0 load overlaps the ||z||^2 pass.
    {
        cp_async16_ca(zs_smem + (lr * BM + lc) * 4, &zb[(size_t)lr * HW + lc]);
        cp_async16_ca(zs_smem + ((lr + 8) * BM + lc) * 4, &zb[(size_t)(lr + 8) * HW + lc]);
        cp_async16_cg(es_smem + (lr * BK + lc) * 4, &g_eT[lr * K_CODES + lc]);
        cp_async16_cg(es_smem + ((lr + 8) * BK + lc) * 4, &g_eT[(lr + 8) * K_CODES + lc]);
        cp_commit();
    }

    // Per-row ||z||^2: sequential over d, rounded squares (exactness-critical).
    if (tid < BM) {
        rmin[tid] = ~0ULL;
        float s = 0.f;
        const float* zp = zb + tid;
        for (int d = 0; d < D_DIM; d++) {
            float v = zp[(size_t)d * HW];
            s = __fadd_rn(s, __fmul_rn(v, v));
        }
        szs[tid] = s;
    }
    __syncthreads();

    float szr[8];
    #pragma unroll
    for (int i = 0; i < 8; i++) szr[i] = szs[ty * 8 + i];

    float minv[8];
    unsigned minj[8];
    #pragma unroll
    for (int i = 0; i < 8; i++) { minv[i] = 3.402823466e38f; minj[i] = 0u; }

    unsigned long long acc2[8][4];             // [row][interleaved pair]

    for (int s = 0; s < NST; s++) {
        const int buf = s & 1;
        const int chunk = s & (NCHUNK - 1);
        const int kt = (s >> 4) * BK;

        cp_wait0();
        __syncthreads();

        if (s + 1 < NST) {
            const int nb = (s + 1) & 1;
            const int nd0 = ((s + 1) & (NCHUNK - 1)) * DCH;
            const int nkt = ((s + 1) >> 4) * BK;
            cp_async16_ca(zs_smem + ((nb * DCH + lr) * BM + lc) * 4,
                          &zb[(size_t)(nd0 + lr) * HW + lc]);
            cp_async16_ca(zs_smem + ((nb * DCH + lr + 8) * BM + lc) * 4,
                          &zb[(size_t)(nd0 + lr + 8) * HW + lc]);
            cp_async16_cg(es_smem + ((nb * DCH + lr) * BK + lc) * 4,
                          &g_eT[(nd0 + lr) * K_CODES + nkt + lc]);
            cp_async16_cg(es_smem + ((nb * DCH + lr + 8) * BK + lc) * 4,
                          &g_eT[(nd0 + lr + 8) * K_CODES + nkt + lc]);
            cp_commit();
        }

        if (chunk == 0) {
            #pragma unroll
            for (int i = 0; i < 8; i++)
                #pragma unroll
                for (int j = 0; j < 4; j++) acc2[i][j] = 0ULL;
        }

        #pragma unroll
        for (int dd = 0; dd < DCH; dd++) {
            float4 za = *(float4*)&zs[buf][dd][ty * 8];
            float4 zc = *(float4*)&zs[buf][dd][ty * 8 + 4];
            // Interleaved pairs: pair p = tx + j2*16 -> address tx*8 + j2*128.
            // Each fixed-j2 warp read is a contiguous 128B block: conflict-free.
            const unsigned long long* ep =
                (const unsigned long long*)&es[buf][dd][0];
            unsigned long long er0 = ep[tx];
            unsigned long long er1 = ep[tx + 16];
            unsigned long long er2v = ep[tx + 32];
            unsigned long long er3 = ep[tx + 48];
            float zr[8] = {za.x, za.y, za.z, za.w, zc.x, zc.y, zc.z, zc.w};
            #pragma unroll
            for (int i = 0; i < 8; i++) {
                unsigned long long zz = pack2(zr[i], zr[i]);
                acc2[i][0] = fma2(zz, er0,  acc2[i][0]);
                acc2[i][1] = fma2(zz, er1,  acc2[i][1]);
                acc2[i][2] = fma2(zz, er2v, acc2[i][2]);
                acc2[i][3] = fma2(zz, er3,  acc2[i][3]);
            }
        }

        if (chunk == NCHUNK - 1) {
            // Same scalar distance + strict-< argmin; codes ascend within
            // a thread (2tx+32*j2), atomicMin handles the global tie-break.
            #pragma unroll
            for (int j2 = 0; j2 < 4; j2++) {
                const int code0 = kt + tx * 2 + j2 * 32;
                const float e2a = g_e2[code0];
                const float e2b = g_e2[code0 + 1];
                #pragma unroll
                for (int i = 0; i < 8; i++) {
                    float dlo, dhi;
                    unpack2(acc2[i][j2], dlo, dhi);
                    float t0 = __fadd_rn(szr[i], e2a);
                    float dist0 = __fmaf_rn(-2.0f, dlo, t0);
                    if (dist0 < minv[i]) { minv[i] = dist0; minj[i] = (unsigned)code0; }
                    float t1 = __fadd_rn(szr[i], e2b);
                    float dist1 = __fmaf_rn(-2.0f, dhi, t1);
                    if (dist1 < minv[i]) { minv[i] = dist1; minj[i] = (unsigned)(code0 + 1); }
                }
            }
        }
    }

    // Cross-thread reduce: packed ordered-float | idx, atomicMin
    // (min picks lowest index on exact ties — reference tie-break).
    #pragma unroll
    for (int i = 0; i < 8; i++) {
        unsigned fb = __float_as_uint(minv[i]);
        fb = (fb & 0x80000000u) ? ~fb : (fb | 0x80000000u);
        unsigned long long p =
            ((unsigned long long)fb << 32) | (unsigned long long)minj[i];
        atomicMin(&rmin[ty * 8 + i], p);
    }
    __syncthreads();

    // Epilogue: 2 threads per row, 128 d's each.
    const int r = tid & 127;
    const int half = tid >> 7;
    const int n = nbase + r;
    const unsigned code = (unsigned)(rmin[r] & 0xFFFFFFFFu);
    if (half == 0) idxf[n] = (float)code;
    const float* erow = emb + (size_t)code * D_DIM;
    float* zqb = zq + (size_t)b * (D_DIM * HW) + hwbase;
    float* lrow = loss + (size_t)n * D_DIM;
    #pragma unroll 4
    for (int sft = 0; sft < D_DIM / 2; sft++) {
        const int d = half * (D_DIM / 2) + sft;
        float zv = zb[(size_t)d * HW + r];
        float ev = __ldg(&erow[d]);
        zqb[(size_t)d * HW + r] = ev;
        float df = __fadd_rn(ev, -zv);
        lrow[d] = __fmul_rn(df, df);
    }
}

extern "C" void kernel_launch(void* const* d_in, const int* in_sizes, int n_in,
                              void* d_out, int out_size) {
    const float* z   = (const float*)d_in[0];   // [32,256,32,32]
    const float* emb = (const float*)d_in[1];   // [1024,256]
    float* out = (float*)d_out;

    const int n_z = in_sizes[0];                // 8388608
    const int N = n_z / D_DIM;                  // 32768

    float* zq   = out;
    float* idxf = out + n_z;
    float* loss = out + n_z + N;

    vq_prep<<<K_CODES, D_DIM>>>(emb);
    vq_main<<<N / BM, 256>>>(z, emb, zq, idxf, loss);
}